// round 14
// baseline (speedup 1.0000x reference)
#include <cuda_runtime.h>
#include <cuda_bf16.h>
#include <cstdint>

// Problem constants
#define PV 50000
#define PE 512
#define PH 512
#define PHD 256
#define PL 2
#define PK 32
#define PB 64
#define PT 256
#define G4 1024      // 4*HD
#define BT (PB*PT)   // 16384

// ---------------- device scratch (no allocation allowed) ----------------
__device__ float g_xA[BT * PE];
__device__ float g_xB[BT * PE];
__device__ float g_gx0[BT * G4];
__device__ float g_gx1[BT * G4];
__device__ float g_ht[2 * 2 * PB * PHD];   // [phase][dir][b][j]
__device__ float g_feats[BT * PK];
__device__ int   g_lens[PB];
__device__ unsigned g_ctrs[16 * 32];       // 16 group counters, 128B apart

// ---------------- f32x2 helpers (packed dual-fp32 FMA, bit-exact fp32) ----
__device__ __forceinline__ unsigned long long f2_fma(unsigned long long a,
                                                     unsigned long long b,
                                                     unsigned long long c) {
    unsigned long long d;
    asm("fma.rn.f32x2 %0, %1, %2, %3;" : "=l"(d) : "l"(a), "l"(b), "l"(c));
    return d;
}
__device__ __forceinline__ float f2_hsum(unsigned long long v) {
    unsigned lo, hi;
    asm("mov.b64 {%0, %1}, %2;" : "=r"(lo), "=r"(hi) : "l"(v));
    return __uint_as_float(lo) + __uint_as_float(hi);
}
__device__ __forceinline__ float f2_lo(unsigned long long v) {
    unsigned lo, hi;
    asm("mov.b64 {%0, %1}, %2;" : "=r"(lo), "=r"(hi) : "l"(v));
    return __uint_as_float(lo);
}
__device__ __forceinline__ float f2_hi(unsigned long long v) {
    unsigned lo, hi;
    asm("mov.b64 {%0, %1}, %2;" : "=r"(lo), "=r"(hi) : "l"(v));
    return __uint_as_float(hi);
}

__device__ __forceinline__ float sigf(float x) { return 1.f / (1.f + __expf(-x)); }

// ---------------- lens (parallel: one block per batch) ----------------
__global__ void k_lens(const int* __restrict__ sent) {
    __shared__ int cnt[8];
    int b = blockIdx.x;
    int t = threadIdx.x;
    int v = (sent[b * PT + t] > 0) ? 1 : 0;
    unsigned m = __ballot_sync(0xffffffffu, v);
    if ((t & 31) == 0) cnt[t >> 5] = __popc(m);
    __syncthreads();
    if (t == 0) {
        int s = 0;
#pragma unroll
        for (int w = 0; w < 8; w++) s += cnt[w];
        g_lens[b] = s;
    }
}

// ---------------- embedding gather + mask ----------------
__global__ void k_embed(const int* __restrict__ sent, const float* __restrict__ embed) {
    int row = blockIdx.x;             // b*T + t
    int tid = threadIdx.x;            // 0..127, one float4 each
    int tok = sent[row];
    float4 v = make_float4(0.f, 0.f, 0.f, 0.f);
    if (tok > 0) v = ((const float4*)(embed + (size_t)tok * PE))[tid];
    ((float4*)(g_xA + (size_t)row * PE))[tid] = v;
}

// ---------------- input-projection GEMM v2 (f32x2, A-dup smem) -----------
// C[m][n] = sum_k A[row(m)][k] * W[n][k] + bi[n] + bh[n]
// Tile 64(M) x 128(N) x 16(K); 256 threads, micro 4x8; 3 CTAs/SM.
// A is stored DUPLICATED in smem (each value twice, adjacent) so the f32x2
// multiplicand pair loads directly via LDS.128 — no packing MOVs.
// z=1 gathers A rows through the reverse-within-length map.
// Also resets the scan's 16 group barrier counters.
#define GBM 64
#define GBN 128
#define GBK 16
#define ASTR 132   // duplicated-A row stride in floats (16B multiple)
__global__ __launch_bounds__(256, 3) void k_gemm_gx(
    const float* __restrict__ Ain,
    const float* __restrict__ w_ih, const float* __restrict__ b_ih,
    const float* __restrict__ b_hh, int layer)
{
    if (threadIdx.x < 16 && blockIdx.x == 0 && blockIdx.y == 0 && blockIdx.z == 0)
        g_ctrs[threadIdx.x * 32] = 0u;

    int z = blockIdx.z;
    const float* W = w_ih + ((size_t)(layer * 2 + z)) * G4 * PE;
    const float* bi = b_ih + (layer * 2 + z) * G4;
    const float* bh = b_hh + (layer * 2 + z) * G4;
    float* C = z ? g_gx1 : g_gx0;

    __shared__ __align__(16) float As2[2][GBK][ASTR];
    __shared__ __align__(16) float Bs[2][GBK][GBN];

    int m0 = blockIdx.y * GBM;
    int n0 = blockIdx.x * GBN;
    int tid = threadIdx.x;
    int tx = tid & 15, ty = tid >> 4;

    // staging identities
    int aRow = tid & 63, aCol = tid >> 6;        // A: 64 rows x 4 float4-cols
    int bRow = tid & 127, bc0 = tid >> 7;        // B: 128 rows x 2 float4-cols per pass
    int bc1 = bc0 + 2;

    // A-row mapping (reverse-within-length for backward direction)
    int arow = m0 + aRow;
    if (z) {
        int bb = arow >> 8, tt = arow & 255;
        int ln = g_lens[bb];
        int pos = (tt < ln) ? (ln - 1 - tt) : tt;
        arow = (bb << 8) + pos;
    }
    const float* Arow = Ain + (size_t)arow * PE + aCol * 4;
    const float* Wr0 = W + (size_t)(n0 + bRow) * PE + bc0 * 4;
    const float* Wr1 = W + (size_t)(n0 + bRow) * PE + bc1 * 4;

    float bsum[8];
#pragma unroll
    for (int j = 0; j < 8; j++) {
        int n = n0 + tx * 8 + j;
        bsum[j] = bi[n] + bh[n];
    }

    unsigned long long acc2[4][4];
#pragma unroll
    for (int i = 0; i < 4; i++)
#pragma unroll
        for (int jp = 0; jp < 4; jp++) acc2[i][jp] = 0ull;

    // prologue: stage tile 0
    {
        float4 av = *(const float4*)(Arow);
        float4 b0v = *(const float4*)(Wr0);
        float4 b1v = *(const float4*)(Wr1);
        int ar2 = 2 * aRow;
        As2[0][aCol * 4 + 0][ar2] = av.x; As2[0][aCol * 4 + 0][ar2 + 1] = av.x;
        As2[0][aCol * 4 + 1][ar2] = av.y; As2[0][aCol * 4 + 1][ar2 + 1] = av.y;
        As2[0][aCol * 4 + 2][ar2] = av.z; As2[0][aCol * 4 + 2][ar2 + 1] = av.z;
        As2[0][aCol * 4 + 3][ar2] = av.w; As2[0][aCol * 4 + 3][ar2 + 1] = av.w;
        Bs[0][bc0 * 4 + 0][bRow] = b0v.x; Bs[0][bc0 * 4 + 1][bRow] = b0v.y;
        Bs[0][bc0 * 4 + 2][bRow] = b0v.z; Bs[0][bc0 * 4 + 3][bRow] = b0v.w;
        Bs[0][bc1 * 4 + 0][bRow] = b1v.x; Bs[0][bc1 * 4 + 1][bRow] = b1v.y;
        Bs[0][bc1 * 4 + 2][bRow] = b1v.z; Bs[0][bc1 * 4 + 3][bRow] = b1v.w;
    }
    __syncthreads();

    int buf = 0;
    for (int k0 = 0; k0 < PE; k0 += GBK) {
        bool nx = (k0 + GBK < PE);
        float4 av, b0v, b1v;
        if (nx) {
            av  = *(const float4*)(Arow + k0 + GBK);
            b0v = *(const float4*)(Wr0 + k0 + GBK);
            b1v = *(const float4*)(Wr1 + k0 + GBK);
        }
#pragma unroll
        for (int kk = 0; kk < GBK; kk++) {
            ulonglong2 a01 = *(const ulonglong2*)&As2[buf][kk][ty * 8];
            ulonglong2 a23 = *(const ulonglong2*)&As2[buf][kk][ty * 8 + 4];
            ulonglong2 b0 = *(const ulonglong2*)&Bs[buf][kk][tx * 8];
            ulonglong2 b1 = *(const ulonglong2*)&Bs[buf][kk][tx * 8 + 4];
            acc2[0][0] = f2_fma(a01.x, b0.x, acc2[0][0]);
            acc2[0][1] = f2_fma(a01.x, b0.y, acc2[0][1]);
            acc2[0][2] = f2_fma(a01.x, b1.x, acc2[0][2]);
            acc2[0][3] = f2_fma(a01.x, b1.y, acc2[0][3]);
            acc2[1][0] = f2_fma(a01.y, b0.x, acc2[1][0]);
            acc2[1][1] = f2_fma(a01.y, b0.y, acc2[1][1]);
            acc2[1][2] = f2_fma(a01.y, b1.x, acc2[1][2]);
            acc2[1][3] = f2_fma(a01.y, b1.y, acc2[1][3]);
            acc2[2][0] = f2_fma(a23.x, b0.x, acc2[2][0]);
            acc2[2][1] = f2_fma(a23.x, b0.y, acc2[2][1]);
            acc2[2][2] = f2_fma(a23.x, b1.x, acc2[2][2]);
            acc2[2][3] = f2_fma(a23.x, b1.y, acc2[2][3]);
            acc2[3][0] = f2_fma(a23.y, b0.x, acc2[3][0]);
            acc2[3][1] = f2_fma(a23.y, b0.y, acc2[3][1]);
            acc2[3][2] = f2_fma(a23.y, b1.x, acc2[3][2]);
            acc2[3][3] = f2_fma(a23.y, b1.y, acc2[3][3]);
        }
        if (nx) {
            int nb = buf ^ 1;
            int ar2 = 2 * aRow;
            As2[nb][aCol * 4 + 0][ar2] = av.x; As2[nb][aCol * 4 + 0][ar2 + 1] = av.x;
            As2[nb][aCol * 4 + 1][ar2] = av.y; As2[nb][aCol * 4 + 1][ar2 + 1] = av.y;
            As2[nb][aCol * 4 + 2][ar2] = av.z; As2[nb][aCol * 4 + 2][ar2 + 1] = av.z;
            As2[nb][aCol * 4 + 3][ar2] = av.w; As2[nb][aCol * 4 + 3][ar2 + 1] = av.w;
            Bs[nb][bc0 * 4 + 0][bRow] = b0v.x; Bs[nb][bc0 * 4 + 1][bRow] = b0v.y;
            Bs[nb][bc0 * 4 + 2][bRow] = b0v.z; Bs[nb][bc0 * 4 + 3][bRow] = b0v.w;
            Bs[nb][bc1 * 4 + 0][bRow] = b1v.x; Bs[nb][bc1 * 4 + 1][bRow] = b1v.y;
            Bs[nb][bc1 * 4 + 2][bRow] = b1v.z; Bs[nb][bc1 * 4 + 3][bRow] = b1v.w;
        }
        __syncthreads();
        buf ^= 1;
    }

#pragma unroll
    for (int i = 0; i < 4; i++) {
        int m = m0 + ty * 4 + i;
        float* cr = C + (size_t)m * G4 + n0 + tx * 8;
        float4 v0 = make_float4(f2_lo(acc2[i][0]) + bsum[0], f2_hi(acc2[i][0]) + bsum[1],
                                f2_lo(acc2[i][1]) + bsum[2], f2_hi(acc2[i][1]) + bsum[3]);
        float4 v1 = make_float4(f2_lo(acc2[i][2]) + bsum[4], f2_hi(acc2[i][2]) + bsum[5],
                                f2_lo(acc2[i][3]) + bsum[6], f2_hi(acc2[i][3]) + bsum[7]);
        *(float4*)(cr + 0) = v0;
        *(float4*)(cr + 4) = v1;
    }
}

// ---------------- persistent recurrent scan (R10 structure, unchanged) ----
#define NB 128
#define WROWS 128                    // 4 gates * 32 units
#define WSTR 260                     // padded row stride (floats)
#define HSTR 260
#define CSTR 257
#define OFF_H (WROWS * WSTR)         // 33280
#define OFF_C (OFF_H + 8 * HSTR)     // 35360
#define SH_FLOATS (OFF_C + 32 * CSTR)  // 43584 floats = 174336 B

__device__ __forceinline__ void gbar(unsigned* ctr, unsigned tgt) {
    __syncthreads();
    if (threadIdx.x == 0) {
        asm volatile("red.release.gpu.global.add.u32 [%0], %1;"
                     :: "l"(ctr), "r"(1u) : "memory");
        unsigned v;
        do {
            asm volatile("ld.acquire.gpu.global.u32 %0, [%1];"
                         : "=r"(v) : "l"(ctr) : "memory");
        } while (v < tgt);
    }
    __syncthreads();
}

__global__ __launch_bounds__(256, 1) void k_scan(const float* __restrict__ w_hh, int layer,
                                                 float* __restrict__ xout)
{
    extern __shared__ float sh[];
    float* w_s = sh;                   // [128][WSTR]
    float* h_s = sh + OFF_H;           // [8][HSTR]
    float* cmb = sh + OFF_C;           // [32][CSTR]

    int bid = blockIdx.x;
    int d  = bid & 1;
    int su = (bid >> 1) & 7;           // unit slice (32 units)
    int gb = bid >> 4;                 // batch group (8 batches)
    int j0 = su * 32;
    int b0g = gb * 8;
    int tid = threadIdx.x;

    int u   = tid >> 3;                // unit 0..31 (mainloop)
    int oct = tid & 7;                 // i-octant

    int uown = tid & 31;
    int biown = tid >> 5;
    int jown  = j0 + uown;
    int bglob = b0g + biown;

    unsigned* ctr = &g_ctrs[(d + gb * 2) * 32];

    const float* whh = w_hh + ((size_t)(layer * 2 + d)) * G4 * PHD;
#pragma unroll
    for (int c = 0; c < 32; c++) {
        int v = tid + c * 256;
        int r = v >> 6, i4 = v & 63;
        int g = r >> 5, uu = r & 31;
        float4 wv = *(const float4*)(whh + (size_t)(g * PHD + j0 + uu) * PHD + i4 * 4);
        *(float4*)&w_s[r * WSTR + i4 * 4] = wv;
    }

    __stcg(&g_ht[((0 * 2 + d) * PB + bglob) * PHD + jown], 0.f);

    int len = g_lens[bglob];
    const float* gxo = (d ? g_gx1 : g_gx0) + (size_t)bglob * PT * G4;
    float* xo = xout + ((size_t)bglob * PT) * PH + d * PHD + jown;

    float ga0 = gxo[jown], ga1 = gxo[PHD + jown],
          ga2 = gxo[2 * PHD + jown], ga3 = gxo[3 * PHD + jown];

    unsigned tgt = 8;
    gbar(ctr, tgt);

    float cst = 0.f;

    const ulonglong2* wb = (const ulonglong2*)w_s;   // row stride WSTR/4 = 65
    const ulonglong2* hb = (const ulonglong2*)h_s;   // row stride HSTR/4 = 65
    int wr0 = (0 * 32 + u) * 65;
    int wr1 = (1 * 32 + u) * 65;
    int wr2 = (2 * 32 + u) * 65;
    int wr3 = (3 * 32 + u) * 65;

    for (int t = 0; t < PT; t++) {
        const float4* hsrc = (const float4*)(g_ht + (size_t)((t & 1) * 2 + d) * PB * PHD
                                             + (size_t)b0g * PHD);
#pragma unroll
        for (int c = 0; c < 2; c++) {
            int v = tid + c * 256;
            float4 hv = __ldcg(hsrc + v);
            int bl = v >> 6, i4 = v & 63;
            *(float4*)&h_s[bl * HSTR + i4 * 4] = hv;
        }
        __syncthreads();

        unsigned long long acc2[4][8];
#pragma unroll
        for (int g = 0; g < 4; g++)
#pragma unroll
            for (int bi = 0; bi < 8; bi++) acc2[g][bi] = 0ull;

#pragma unroll 2
        for (int k = 0; k < 8; k++) {
            int i4 = oct + 8 * k;
            ulonglong2 x0 = wb[wr0 + i4];
            ulonglong2 x1 = wb[wr1 + i4];
            ulonglong2 x2 = wb[wr2 + i4];
            ulonglong2 x3 = wb[wr3 + i4];
#pragma unroll
            for (int bi = 0; bi < 8; bi++) {
                ulonglong2 hv = hb[bi * 65 + i4];
                acc2[0][bi] = f2_fma(hv.x, x0.x, acc2[0][bi]);
                acc2[0][bi] = f2_fma(hv.y, x0.y, acc2[0][bi]);
                acc2[1][bi] = f2_fma(hv.x, x1.x, acc2[1][bi]);
                acc2[1][bi] = f2_fma(hv.y, x1.y, acc2[1][bi]);
                acc2[2][bi] = f2_fma(hv.x, x2.x, acc2[2][bi]);
                acc2[2][bi] = f2_fma(hv.y, x2.y, acc2[2][bi]);
                acc2[3][bi] = f2_fma(hv.x, x3.x, acc2[3][bi]);
                acc2[3][bi] = f2_fma(hv.y, x3.y, acc2[3][bi]);
            }
        }

#pragma unroll
        for (int g = 0; g < 4; g++)
#pragma unroll
            for (int bi = 0; bi < 8; bi++)
                cmb[(oct * 4 + g) * CSTR + bi * 32 + u] = f2_hsum(acc2[g][bi]);
        __syncthreads();

        float a0 = ga0, a1 = ga1, a2 = ga2, a3 = ga3;
#pragma unroll
        for (int o2 = 0; o2 < 8; o2++) {
            a0 += cmb[(o2 * 4 + 0) * CSTR + tid];
            a1 += cmb[(o2 * 4 + 1) * CSTR + tid];
            a2 += cmb[(o2 * 4 + 2) * CSTR + tid];
            a3 += cmb[(o2 * 4 + 3) * CSTR + tid];
        }
        float ig = sigf(a0), fg = sigf(a1), gg = tanhf(a2), og = sigf(a3);
        cst = fg * cst + ig * gg;
        float h = og * tanhf(cst);
        __stcg(&g_ht[((((t + 1) & 1) * 2 + d) * PB + bglob) * PHD + jown], h);

        int pos = (d == 0) ? t : ((t < len) ? (len - 1 - t) : t);
        xo[(size_t)pos * PH] = (t < len) ? h : 0.f;

        if (t < PT - 1) {
            const float* gxt = gxo + (size_t)(t + 1) * G4;
            ga0 = gxt[jown]; ga1 = gxt[PHD + jown];
            ga2 = gxt[2 * PHD + jown]; ga3 = gxt[3 * PHD + jown];
            tgt += 8;
            gbar(ctr, tgt);
        }
    }
}

// ---------------- FC: feats = x @ fc_w.T + fc_b (f32x2) ----------------
__global__ void k_feats(const float* __restrict__ x2, const float* __restrict__ fc_w,
                        const float* __restrict__ fc_b)
{
    int w = threadIdx.x >> 5, lane = threadIdx.x & 31;
    int row = blockIdx.x * 8 + w;
    const ulonglong2* xr = (const ulonglong2*)(x2 + (size_t)row * PH);
    const ulonglong2* wr = (const ulonglong2*)(fc_w + (size_t)lane * PH);
    unsigned long long acc2 = 0ull;
#pragma unroll 8
    for (int i = 0; i < PH / 4; i++) {
        ulonglong2 xv = xr[i];
        ulonglong2 wv = __ldg(wr + i);
        acc2 = f2_fma(xv.x, wv.x, acc2);
        acc2 = f2_fma(xv.y, wv.y, acc2);
    }
    g_feats[(size_t)row * PK + lane] = fc_b[lane] + f2_hsum(acc2);
}

// ---------------- Viterbi decode (register delta + shfl broadcast) -------
__global__ void k_viterbi(const float* __restrict__ st, const float* __restrict__ tr,
                          const float* __restrict__ et,
                          float* __restrict__ scores_out, float* __restrict__ tags_out)
{
    int b = blockIdx.x;
    int lane = threadIdx.x;  // 0..31 == tag index
    __shared__ float fs[PT][PK];          // staged feats row block (32 KB)
    __shared__ float fin_s[PK];
    __shared__ unsigned char ptr_s[PT][PK];

    // this lane's transition column in registers: trc[kp] = tr[kp][lane]
    float trc[PK];
#pragma unroll
    for (int kp = 0; kp < PK; kp++) trc[kp] = tr[kp * PK + lane];

    // stage the whole feats block for this batch (coalesced float4)
    const float4* fb4 = (const float4*)(g_feats + (size_t)b * PT * PK);
    float4* fs4 = (float4*)fs;
    for (int i = lane; i < PT * PK / 4; i += 32) fs4[i] = fb4[i];
    __syncwarp();

    float dl = st[lane] + fs[0][lane];
    int len = g_lens[b];

    for (int t = 1; t < PT; t++) {
        float best = -3.4e38f; int arg = 0;
#pragma unroll
        for (int kp = 0; kp < PK; kp++) {
            float v = __shfl_sync(0xffffffffu, dl, kp) + trc[kp];
            if (v > best) { best = v; arg = kp; }
        }
        float nd; int p;
        if (t < len) { nd = best + fs[t][lane]; p = arg; }
        else         { nd = dl; p = lane; }
        ptr_s[t][lane] = (unsigned char)p;
        dl = nd;   // shfl_sync above is the intra-warp sync point
    }

    fin_s[lane] = dl + et[lane];
    __syncwarp();

    if (lane == 0) {
        float best = -3.4e38f; int last = 0;
        for (int k = 0; k < PK; k++)
            if (fin_s[k] > best) { best = fin_s[k]; last = k; }
        if (scores_out) scores_out[b] = best;
        if (tags_out) {
            float* tg = tags_out + (size_t)b * PT;
            tg[PT - 1] = (PT - 1 < len) ? (float)last : 0.f;
            int cur = last;
            for (int t = PT - 1; t >= 1; t--) {
                int prev = (int)ptr_s[t][cur];
                cur = prev;
                tg[t - 1] = (t - 1 < len) ? (float)prev : 0.f;
            }
        }
    }
}

// ---------------- launch ----------------
extern "C" void kernel_launch(void* const* d_in, const int* in_sizes, int n_in,
                              void* d_out, int out_size)
{
    const int*   sent  = (const int*)d_in[0];
    const float* embed = (const float*)d_in[1];
    const float* w_ih  = (const float*)d_in[2];
    const float* w_hh  = (const float*)d_in[3];
    const float* b_ih  = (const float*)d_in[4];
    const float* b_hh  = (const float*)d_in[5];
    const float* fc_w  = (const float*)d_in[6];
    const float* fc_b  = (const float*)d_in[7];
    const float* st    = (const float*)d_in[8];
    const float* tr    = (const float*)d_in[9];
    const float* et    = (const float*)d_in[10];

    float* out = (float*)d_out;
    float* scores_ptr = nullptr;
    float* tags_ptr = nullptr;
    if (out_size >= PB + BT)      { scores_ptr = out; tags_ptr = out + PB; }
    else if (out_size == BT)      { tags_ptr = out; }
    else                          { scores_ptr = out; }

    float *xA, *xB;
    cudaGetSymbolAddress((void**)&xA, g_xA);
    cudaGetSymbolAddress((void**)&xB, g_xB);

    cudaFuncSetAttribute(k_scan, cudaFuncAttributeMaxDynamicSharedMemorySize,
                         SH_FLOATS * (int)sizeof(float));

    k_lens<<<PB, 256>>>(sent);
    k_embed<<<dim3(BT), 128>>>(sent, embed);

    for (int l = 0; l < PL; l++) {
        float* xin  = (l == 0) ? xA : xB;
        float* xout = (l == 0) ? xB : xA;
        k_gemm_gx<<<dim3(G4 / GBN, BT / GBM, 2), 256>>>(xin, w_ih, b_ih, b_hh, l);
        k_scan<<<NB, 256, SH_FLOATS * (int)sizeof(float)>>>(w_hh, l, xout);
    }

    k_feats<<<BT / 8, 256>>>(xA, fc_w, fc_b);
    k_viterbi<<<PB, 32>>>(st, tr, et, scores_ptr, tags_ptr);
}

// round 15
// speedup vs baseline: 1.4471x; 1.4471x over previous
#include <cuda_runtime.h>
#include <cuda_bf16.h>
#include <cstdint>

// Problem constants
#define PV 50000
#define PE 512
#define PH 512
#define PHD 256
#define PL 2
#define PK 32
#define PB 64
#define PT 256
#define G4 1024      // 4*HD
#define BT (PB*PT)   // 16384

// ---------------- device scratch (no allocation allowed) ----------------
__device__ float g_xA[BT * PE];
__device__ float g_xB[BT * PE];
__device__ float g_gx0[BT * G4];
__device__ float g_gx1[BT * G4];
__device__ float g_ht[2 * 2 * PB * PHD];   // [phase][dir][b][j]
__device__ float g_feats[BT * PK];
__device__ int   g_lens[PB];
__device__ unsigned g_ctrs[16 * 32];       // 16 group counters, 128B apart

// ---------------- f32x2 helpers (packed dual-fp32 FMA, bit-exact fp32) ----
__device__ __forceinline__ unsigned long long f2_pack_dup(float x) {
    unsigned long long r;
    unsigned u = __float_as_uint(x);
    asm("mov.b64 %0, {%1, %1};" : "=l"(r) : "r"(u));
    return r;
}
__device__ __forceinline__ unsigned long long f2_fma(unsigned long long a,
                                                     unsigned long long b,
                                                     unsigned long long c) {
    unsigned long long d;
    asm("fma.rn.f32x2 %0, %1, %2, %3;" : "=l"(d) : "l"(a), "l"(b), "l"(c));
    return d;
}
__device__ __forceinline__ float f2_hsum(unsigned long long v) {
    unsigned lo, hi;
    asm("mov.b64 {%0, %1}, %2;" : "=r"(lo), "=r"(hi) : "l"(v));
    return __uint_as_float(lo) + __uint_as_float(hi);
}
__device__ __forceinline__ float f2_lo(unsigned long long v) {
    unsigned lo, hi;
    asm("mov.b64 {%0, %1}, %2;" : "=r"(lo), "=r"(hi) : "l"(v));
    return __uint_as_float(lo);
}
__device__ __forceinline__ float f2_hi(unsigned long long v) {
    unsigned lo, hi;
    asm("mov.b64 {%0, %1}, %2;" : "=r"(lo), "=r"(hi) : "l"(v));
    return __uint_as_float(hi);
}

__device__ __forceinline__ float sigf(float x) { return 1.f / (1.f + __expf(-x)); }

// ---------------- lens (parallel: one block per batch) ----------------
__global__ void k_lens(const int* __restrict__ sent) {
    __shared__ int cnt[8];
    int b = blockIdx.x;
    int t = threadIdx.x;
    int v = (sent[b * PT + t] > 0) ? 1 : 0;
    unsigned m = __ballot_sync(0xffffffffu, v);
    if ((t & 31) == 0) cnt[t >> 5] = __popc(m);
    __syncthreads();
    if (t == 0) {
        int s = 0;
#pragma unroll
        for (int w = 0; w < 8; w++) s += cnt[w];
        g_lens[b] = s;
    }
}

// ---------------- embedding gather + mask ----------------
__global__ void k_embed(const int* __restrict__ sent, const float* __restrict__ embed) {
    int row = blockIdx.x;             // b*T + t
    int tid = threadIdx.x;            // 0..127, one float4 each
    int tok = sent[row];
    float4 v = make_float4(0.f, 0.f, 0.f, 0.f);
    if (tok > 0) v = ((const float4*)(embed + (size_t)tok * PE))[tid];
    ((float4*)(g_xA + (size_t)row * PE))[tid] = v;
}

// ---------------- input-projection GEMM (f32x2, GBK=16) ----------------
// C[m][n] = sum_k A[row(m)][k] * W[n][k] + bi[n] + bh[n]
// z=1 gathers A rows through the reverse-within-length map.
// Also resets the scan's 16 group barrier counters.
#define GBM 128
#define GBN 128
#define GBK 16
__global__ __launch_bounds__(256, 2) void k_gemm_gx(
    const float* __restrict__ Ain,
    const float* __restrict__ w_ih, const float* __restrict__ b_ih,
    const float* __restrict__ b_hh, int layer)
{
    if (threadIdx.x < 16 && blockIdx.x == 0 && blockIdx.y == 0 && blockIdx.z == 0)
        g_ctrs[threadIdx.x * 32] = 0u;

    int z = blockIdx.z;
    const float* W = w_ih + ((size_t)(layer * 2 + z)) * G4 * PE;
    const float* bi = b_ih + (layer * 2 + z) * G4;
    const float* bh = b_hh + (layer * 2 + z) * G4;
    float* C = z ? g_gx1 : g_gx0;

    __shared__ __align__(16) float As[2][GBK][GBM];
    __shared__ __align__(16) float Bs[2][GBK][GBN];

    int m0 = blockIdx.y * GBM;
    int n0 = blockIdx.x * GBN;
    int tid = threadIdx.x;
    int lr = tid >> 1;                 // row 0..127
    int lc = (tid & 1) * 4;            // col 0..7 (first half of k-slice)
    int tx = tid & 15, ty = tid >> 4;

    // A-row mapping (reverse-within-length for backward direction)
    int arow = m0 + lr;
    if (z) {
        int bb = arow >> 8, tt = arow & 255;
        int ln = g_lens[bb];
        int pos = (tt < ln) ? (ln - 1 - tt) : tt;
        arow = (bb << 8) + pos;
    }
    const float* Arow = Ain + (size_t)arow * PE;
    const float* Wrow = W + (size_t)(n0 + lr) * PE;

    float bsum[8];
#pragma unroll
    for (int j = 0; j < 8; j++) {
        int n = n0 + tx * 8 + j;
        bsum[j] = bi[n] + bh[n];
    }

    unsigned long long acc2[8][4];
#pragma unroll
    for (int i = 0; i < 8; i++)
#pragma unroll
        for (int jp = 0; jp < 4; jp++) acc2[i][jp] = 0ull;

    // prologue: stage tile 0 (two float4 per operand per thread)
    {
        float4 a0v = *(const float4*)(Arow + lc);
        float4 a1v = *(const float4*)(Arow + lc + 8);
        float4 b0v = *(const float4*)(Wrow + lc);
        float4 b1v = *(const float4*)(Wrow + lc + 8);
        As[0][lc + 0][lr] = a0v.x; As[0][lc + 1][lr] = a0v.y; As[0][lc + 2][lr] = a0v.z; As[0][lc + 3][lr] = a0v.w;
        As[0][lc + 8][lr] = a1v.x; As[0][lc + 9][lr] = a1v.y; As[0][lc +10][lr] = a1v.z; As[0][lc +11][lr] = a1v.w;
        Bs[0][lc + 0][lr] = b0v.x; Bs[0][lc + 1][lr] = b0v.y; Bs[0][lc + 2][lr] = b0v.z; Bs[0][lc + 3][lr] = b0v.w;
        Bs[0][lc + 8][lr] = b1v.x; Bs[0][lc + 9][lr] = b1v.y; Bs[0][lc +10][lr] = b1v.z; Bs[0][lc +11][lr] = b1v.w;
    }
    __syncthreads();

    int buf = 0;
    for (int k0 = 0; k0 < PE; k0 += GBK) {
        bool nx = (k0 + GBK < PE);
        float4 a0v, a1v, b0v, b1v;
        if (nx) {
            a0v = *(const float4*)(Arow + k0 + GBK + lc);
            a1v = *(const float4*)(Arow + k0 + GBK + lc + 8);
            b0v = *(const float4*)(Wrow + k0 + GBK + lc);
            b1v = *(const float4*)(Wrow + k0 + GBK + lc + 8);
        }
#pragma unroll
        for (int kk = 0; kk < GBK; kk++) {
            float4 a0 = *(const float4*)&As[buf][kk][ty * 8];
            float4 a1 = *(const float4*)&As[buf][kk][ty * 8 + 4];
            ulonglong2 b0 = *(const ulonglong2*)&Bs[buf][kk][tx * 8];
            ulonglong2 b1 = *(const ulonglong2*)&Bs[buf][kk][tx * 8 + 4];
            unsigned long long ad[8];
            ad[0] = f2_pack_dup(a0.x); ad[1] = f2_pack_dup(a0.y);
            ad[2] = f2_pack_dup(a0.z); ad[3] = f2_pack_dup(a0.w);
            ad[4] = f2_pack_dup(a1.x); ad[5] = f2_pack_dup(a1.y);
            ad[6] = f2_pack_dup(a1.z); ad[7] = f2_pack_dup(a1.w);
#pragma unroll
            for (int i = 0; i < 8; i++) {
                acc2[i][0] = f2_fma(ad[i], b0.x, acc2[i][0]);
                acc2[i][1] = f2_fma(ad[i], b0.y, acc2[i][1]);
                acc2[i][2] = f2_fma(ad[i], b1.x, acc2[i][2]);
                acc2[i][3] = f2_fma(ad[i], b1.y, acc2[i][3]);
            }
        }
        if (nx) {
            int nb = buf ^ 1;
            As[nb][lc + 0][lr] = a0v.x; As[nb][lc + 1][lr] = a0v.y; As[nb][lc + 2][lr] = a0v.z; As[nb][lc + 3][lr] = a0v.w;
            As[nb][lc + 8][lr] = a1v.x; As[nb][lc + 9][lr] = a1v.y; As[nb][lc +10][lr] = a1v.z; As[nb][lc +11][lr] = a1v.w;
            Bs[nb][lc + 0][lr] = b0v.x; Bs[nb][lc + 1][lr] = b0v.y; Bs[nb][lc + 2][lr] = b0v.z; Bs[nb][lc + 3][lr] = b0v.w;
            Bs[nb][lc + 8][lr] = b1v.x; Bs[nb][lc + 9][lr] = b1v.y; Bs[nb][lc +10][lr] = b1v.z; Bs[nb][lc +11][lr] = b1v.w;
        }
        __syncthreads();
        buf ^= 1;
    }

#pragma unroll
    for (int i = 0; i < 8; i++) {
        int m = m0 + ty * 8 + i;
        float* cr = C + (size_t)m * G4 + n0 + tx * 8;
        float4 v0 = make_float4(f2_lo(acc2[i][0]) + bsum[0], f2_hi(acc2[i][0]) + bsum[1],
                                f2_lo(acc2[i][1]) + bsum[2], f2_hi(acc2[i][1]) + bsum[3]);
        float4 v1 = make_float4(f2_lo(acc2[i][2]) + bsum[4], f2_hi(acc2[i][2]) + bsum[5],
                                f2_lo(acc2[i][3]) + bsum[6], f2_hi(acc2[i][3]) + bsum[7]);
        *(float4*)(cr + 0) = v0;
        *(float4*)(cr + 4) = v1;
    }
}

// ---------------- persistent recurrent scan (R10 structure) ----------------
// Block = (dir, 32-unit slice, 8-batch group): 2*8*8 = 128 blocks.
// Cross-block dependency only among the 8 blocks sharing (dir, batch-group)
// -> 16 independent group barriers of 8 CTAs each (L2 counters).
// Owner mapping: col = bi*32 + u  =>  per warp batch is FIXED and units are
// CONSECUTIVE, so gx loads / h stores / xout stores are 128B-coalesced.
#define NB 128
#define WROWS 128                    // 4 gates * 32 units
#define WSTR 260                     // padded row stride (floats)
#define HSTR 260
#define CSTR 257
#define OFF_H (WROWS * WSTR)         // 33280
#define OFF_C (OFF_H + 8 * HSTR)     // 35360
#define SH_FLOATS (OFF_C + 32 * CSTR)  // 43584 floats = 174336 B

__device__ __forceinline__ void gbar(unsigned* ctr, unsigned tgt) {
    __syncthreads();
    if (threadIdx.x == 0) {
        asm volatile("red.release.gpu.global.add.u32 [%0], %1;"
                     :: "l"(ctr), "r"(1u) : "memory");
        unsigned v;
        do {
            asm volatile("ld.acquire.gpu.global.u32 %0, [%1];"
                         : "=r"(v) : "l"(ctr) : "memory");
        } while (v < tgt);
    }
    __syncthreads();
}

__global__ __launch_bounds__(256, 1) void k_scan(const float* __restrict__ w_hh, int layer,
                                                 float* __restrict__ xout)
{
    extern __shared__ float sh[];
    float* w_s = sh;                   // [128][WSTR]
    float* h_s = sh + OFF_H;           // [8][HSTR]
    float* cmb = sh + OFF_C;           // [32][CSTR]

    int bid = blockIdx.x;
    int d  = bid & 1;
    int su = (bid >> 1) & 7;           // unit slice (32 units)
    int gb = bid >> 4;                 // batch group (8 batches)
    int j0 = su * 32;
    int b0g = gb * 8;
    int tid = threadIdx.x;

    // mainloop identity
    int u   = tid >> 3;                // unit 0..31
    int oct = tid & 7;                 // i-octant

    // owner identity: col = bi*32 + u  (warp: bi fixed, u consecutive)
    int uown = tid & 31;
    int biown = tid >> 5;
    int jown  = j0 + uown;
    int bglob = b0g + biown;

    unsigned* ctr = &g_ctrs[(d + gb * 2) * 32];

    // load W_hh slice: rows r = g*32+u  ->  W[g][j0+u][0..255]
    const float* whh = w_hh + ((size_t)(layer * 2 + d)) * G4 * PHD;
#pragma unroll
    for (int c = 0; c < 32; c++) {
        int v = tid + c * 256;         // 8192 float4 total
        int r = v >> 6, i4 = v & 63;
        int g = r >> 5, uu = r & 31;
        float4 wv = *(const float4*)(whh + (size_t)(g * PHD + j0 + uu) * PHD + i4 * 4);
        *(float4*)&w_s[r * WSTR + i4 * 4] = wv;
    }

    // zero phase-0 hidden state (owner covers (d, bglob, jown) exactly once)
    __stcg(&g_ht[((0 * 2 + d) * PB + bglob) * PHD + jown], 0.f);

    int len = g_lens[bglob];
    const float* gxo = (d ? g_gx1 : g_gx0) + (size_t)bglob * PT * G4;
    float* xo = xout + ((size_t)bglob * PT) * PH + d * PHD + jown;

    // prefetch gx for t=0 (coalesced: 128B per warp per gate)
    float ga0 = gxo[jown], ga1 = gxo[PHD + jown],
          ga2 = gxo[2 * PHD + jown], ga3 = gxo[3 * PHD + jown];

    unsigned tgt = 8;
    gbar(ctr, tgt);

    float cst = 0.f;

    const ulonglong2* wb = (const ulonglong2*)w_s;   // row stride WSTR/4 = 65
    const ulonglong2* hb = (const ulonglong2*)h_s;   // row stride HSTR/4 = 65
    int wr0 = (0 * 32 + u) * 65;
    int wr1 = (1 * 32 + u) * 65;
    int wr2 = (2 * 32 + u) * 65;
    int wr3 = (3 * 32 + u) * 65;

    for (int t = 0; t < PT; t++) {
        // stage h for this block's 8 batches (8 KB), coalesced
        const float4* hsrc = (const float4*)(g_ht + (size_t)((t & 1) * 2 + d) * PB * PHD
                                             + (size_t)b0g * PHD);
#pragma unroll
        for (int c = 0; c < 2; c++) {
            int v = tid + c * 256;     // 512 float4 total; v = bl*64 + i4
            float4 hv = __ldcg(hsrc + v);
            int bl = v >> 6, i4 = v & 63;
            *(float4*)&h_s[bl * HSTR + i4 * 4] = hv;
        }
        __syncthreads();

        // partial matvec over this thread's i-octant: acc[4 gates][8 batches]
        unsigned long long acc2[4][8];
#pragma unroll
        for (int g = 0; g < 4; g++)
#pragma unroll
            for (int bi = 0; bi < 8; bi++) acc2[g][bi] = 0ull;

#pragma unroll 2
        for (int k = 0; k < 8; k++) {
            int i4 = oct + 8 * k;
            ulonglong2 x0 = wb[wr0 + i4];
            ulonglong2 x1 = wb[wr1 + i4];
            ulonglong2 x2 = wb[wr2 + i4];
            ulonglong2 x3 = wb[wr3 + i4];
#pragma unroll
            for (int bi = 0; bi < 8; bi++) {
                ulonglong2 hv = hb[bi * 65 + i4];
                acc2[0][bi] = f2_fma(hv.x, x0.x, acc2[0][bi]);
                acc2[0][bi] = f2_fma(hv.y, x0.y, acc2[0][bi]);
                acc2[1][bi] = f2_fma(hv.x, x1.x, acc2[1][bi]);
                acc2[1][bi] = f2_fma(hv.y, x1.y, acc2[1][bi]);
                acc2[2][bi] = f2_fma(hv.x, x2.x, acc2[2][bi]);
                acc2[2][bi] = f2_fma(hv.y, x2.y, acc2[2][bi]);
                acc2[3][bi] = f2_fma(hv.x, x3.x, acc2[3][bi]);
                acc2[3][bi] = f2_fma(hv.y, x3.y, acc2[3][bi]);
            }
        }

        // scatter partials: row = oct*4+g, col = bi*32 + u (conflict-free)
#pragma unroll
        for (int g = 0; g < 4; g++)
#pragma unroll
            for (int bi = 0; bi < 8; bi++)
                cmb[(oct * 4 + g) * CSTR + bi * 32 + u] = f2_hsum(acc2[g][bi]);
        __syncthreads();

        // owner combine (owner col = biown*32 + uown == tid) + nonlinearity
        float a0 = ga0, a1 = ga1, a2 = ga2, a3 = ga3;
#pragma unroll
        for (int o2 = 0; o2 < 8; o2++) {
            a0 += cmb[(o2 * 4 + 0) * CSTR + tid];
            a1 += cmb[(o2 * 4 + 1) * CSTR + tid];
            a2 += cmb[(o2 * 4 + 2) * CSTR + tid];
            a3 += cmb[(o2 * 4 + 3) * CSTR + tid];
        }
        float ig = sigf(a0), fg = sigf(a1), gg = tanhf(a2), og = sigf(a3);
        cst = fg * cst + ig * gg;
        float h = og * tanhf(cst);
        __stcg(&g_ht[((((t + 1) & 1) * 2 + d) * PB + bglob) * PHD + jown], h);

        int pos = (d == 0) ? t : ((t < len) ? (len - 1 - t) : t);
        xo[(size_t)pos * PH] = (t < len) ? h : 0.f;   // coalesced 128B/warp

        if (t < PT - 1) {
            const float* gxt = gxo + (size_t)(t + 1) * G4;
            ga0 = gxt[jown]; ga1 = gxt[PHD + jown];
            ga2 = gxt[2 * PHD + jown]; ga3 = gxt[3 * PHD + jown];
            tgt += 8;
            gbar(ctr, tgt);
        }
    }
}

// ---------------- FC: feats = x @ fc_w.T + fc_b (f32x2) ----------------
__global__ void k_feats(const float* __restrict__ x2, const float* __restrict__ fc_w,
                        const float* __restrict__ fc_b)
{
    int w = threadIdx.x >> 5, lane = threadIdx.x & 31;
    int row = blockIdx.x * 8 + w;
    const ulonglong2* xr = (const ulonglong2*)(x2 + (size_t)row * PH);
    const ulonglong2* wr = (const ulonglong2*)(fc_w + (size_t)lane * PH);
    unsigned long long acc2 = 0ull;
#pragma unroll 8
    for (int i = 0; i < PH / 4; i++) {
        ulonglong2 xv = xr[i];
        ulonglong2 wv = __ldg(wr + i);
        acc2 = f2_fma(xv.x, wv.x, acc2);
        acc2 = f2_fma(xv.y, wv.y, acc2);
    }
    g_feats[(size_t)row * PK + lane] = fc_b[lane] + f2_hsum(acc2);
}

// ---------------- Viterbi decode (register delta + shfl broadcast) -------
__global__ void k_viterbi(const float* __restrict__ st, const float* __restrict__ tr,
                          const float* __restrict__ et,
                          float* __restrict__ scores_out, float* __restrict__ tags_out)
{
    int b = blockIdx.x;
    int lane = threadIdx.x;  // 0..31 == tag index
    __shared__ float fs[PT][PK];          // staged feats row block (32 KB)
    __shared__ float fin_s[PK];
    __shared__ unsigned char ptr_s[PT][PK];

    // this lane's transition column in registers: trc[kp] = tr[kp][lane]
    float trc[PK];
#pragma unroll
    for (int kp = 0; kp < PK; kp++) trc[kp] = tr[kp * PK + lane];

    // stage the whole feats block for this batch (coalesced float4)
    const float4* fb4 = (const float4*)(g_feats + (size_t)b * PT * PK);
    float4* fs4 = (float4*)fs;
    for (int i = lane; i < PT * PK / 4; i += 32) fs4[i] = fb4[i];
    __syncwarp();

    float dl = st[lane] + fs[0][lane];
    int len = g_lens[b];

    for (int t = 1; t < PT; t++) {
        float best = -3.4e38f; int arg = 0;
#pragma unroll
        for (int kp = 0; kp < PK; kp++) {
            float v = __shfl_sync(0xffffffffu, dl, kp) + trc[kp];
            if (v > best) { best = v; arg = kp; }
        }
        float nd; int p;
        if (t < len) { nd = best + fs[t][lane]; p = arg; }
        else         { nd = dl; p = lane; }
        ptr_s[t][lane] = (unsigned char)p;
        dl = nd;   // shfl_sync above is the intra-warp sync point
    }

    fin_s[lane] = dl + et[lane];
    __syncwarp();

    if (lane == 0) {
        float best = -3.4e38f; int last = 0;
        for (int k = 0; k < PK; k++)
            if (fin_s[k] > best) { best = fin_s[k]; last = k; }
        if (scores_out) scores_out[b] = best;
        if (tags_out) {
            float* tg = tags_out + (size_t)b * PT;
            tg[PT - 1] = (PT - 1 < len) ? (float)last : 0.f;
            int cur = last;
            for (int t = PT - 1; t >= 1; t--) {
                int prev = (int)ptr_s[t][cur];
                cur = prev;
                tg[t - 1] = (t - 1 < len) ? (float)prev : 0.f;
            }
        }
    }
}

// ---------------- launch ----------------
extern "C" void kernel_launch(void* const* d_in, const int* in_sizes, int n_in,
                              void* d_out, int out_size)
{
    const int*   sent  = (const int*)d_in[0];
    const float* embed = (const float*)d_in[1];
    const float* w_ih  = (const float*)d_in[2];
    const float* w_hh  = (const float*)d_in[3];
    const float* b_ih  = (const float*)d_in[4];
    const float* b_hh  = (const float*)d_in[5];
    const float* fc_w  = (const float*)d_in[6];
    const float* fc_b  = (const float*)d_in[7];
    const float* st    = (const float*)d_in[8];
    const float* tr    = (const float*)d_in[9];
    const float* et    = (const float*)d_in[10];

    float* out = (float*)d_out;
    float* scores_ptr = nullptr;
    float* tags_ptr = nullptr;
    if (out_size >= PB + BT)      { scores_ptr = out; tags_ptr = out + PB; }
    else if (out_size == BT)      { tags_ptr = out; }
    else                          { scores_ptr = out; }

    float *xA, *xB;
    cudaGetSymbolAddress((void**)&xA, g_xA);
    cudaGetSymbolAddress((void**)&xB, g_xB);

    cudaFuncSetAttribute(k_scan, cudaFuncAttributeMaxDynamicSharedMemorySize,
                         SH_FLOATS * (int)sizeof(float));

    k_lens<<<PB, 256>>>(sent);
    k_embed<<<dim3(BT), 128>>>(sent, embed);

    for (int l = 0; l < PL; l++) {
        float* xin  = (l == 0) ? xA : xB;
        float* xout = (l == 0) ? xB : xA;
        k_gemm_gx<<<dim3(G4 / GBN, BT / GBM, 2), 256>>>(xin, w_ih, b_ih, b_hh, l);
        k_scan<<<NB, 256, SH_FLOATS * (int)sizeof(float)>>>(w_hh, l, xout);
    }

    k_feats<<<BT / 8, 256>>>(xA, fc_w, fc_b);
    k_viterbi<<<PB, 32>>>(st, tr, et, scores_ptr, tags_ptr);
}